// round 1
// baseline (speedup 1.0000x reference)
#include <cuda_runtime.h>

// Problem constants (fixed by setup_inputs)
#define CC      4
#define HH      256
#define WW      256
#define PS      7
#define STRIDE  2
#define EE      32
#define OO      32
#define NN      125                  // patches per side: (256-7)/2+1
#define NQ      (NN * NN)            // 15625 queries/patches
#define DD      196                  // C*ps*ps
#define DD4     49                   // DD/4 float4 chunks (784B row, 16B aligned)
#define DIST_SCALE 10.0f

// Scratch (allocation-free rule: __device__ globals)
__device__ float g_XP[NQ * DD];      // unfolded patches, row-major [q][d]
__device__ float g_Z [NQ * DD];      // aggregated patches

// ---------------------------------------------------------------------------
// K0: unfold x (C,H,W) -> XP[q][d], d = c*49 + r*7 + s, q = i*125 + j
// ---------------------------------------------------------------------------
__global__ void unfold_kernel(const float* __restrict__ x) {
    int idx = blockIdx.x * blockDim.x + threadIdx.x;
    if (idx >= NQ * DD) return;
    int q  = idx / DD;
    int d  = idx - q * DD;
    int c  = d / 49;
    int rs = d - c * 49;
    int r  = rs / 7;
    int s  = rs - r * 7;
    int i  = q / NN;
    int j  = q - i * NN;
    g_XP[idx] = x[c * (HH * WW) + (i * STRIDE + r) * WW + (j * STRIDE + s)];
}

// ---------------------------------------------------------------------------
// K1: fused distance + softmax + weighted aggregation. One 64-thread CTA per q.
//   warp 0 : per-o squared distance (float4 loads of xe rows) + shuffle softmax
//   tid<49 : z[q] chunk accumulate (LD.128 gathers from XP)
// ---------------------------------------------------------------------------
__global__ __launch_bounds__(64) void agg_kernel(const float* __restrict__ xe,
                                                 const float* __restrict__ ye,
                                                 const int*   __restrict__ inds) {
    const int q   = blockIdx.x;
    const int tid = threadIdx.x;

    __shared__ __align__(16) float s_ye[EE];
    __shared__ float s_w[OO];
    __shared__ int   s_p[OO];

    if (tid < OO) {                       // OO == EE == 32: all of warp 0
        s_ye[tid] = ye[q * EE + tid];
        __syncwarp();

        const int p = inds[q * OO + tid];
        s_p[tid] = p;

        const float4* xr = reinterpret_cast<const float4*>(xe + p * EE);
        const float4* yr = reinterpret_cast<const float4*>(s_ye);
        float d2 = 0.f;
#pragma unroll
        for (int k = 0; k < EE / 4; k++) {
            float4 a = xr[k];
            float4 b = yr[k];
            float dx = a.x - b.x, dy = a.y - b.y;
            float dz = a.z - b.z, dw = a.w - b.w;
            d2 += dx * dx + dy * dy + dz * dz + dw * dw;
        }

        // softmax over the 32 lanes of warp 0: max of (-s*d2) <=> min of d2
        float m = d2;
#pragma unroll
        for (int off = 16; off; off >>= 1)
            m = fminf(m, __shfl_xor_sync(0xFFFFFFFFu, m, off));
        float ev = __expf(-DIST_SCALE * (d2 - m));
        float sum = ev;
#pragma unroll
        for (int off = 16; off; off >>= 1)
            sum += __shfl_xor_sync(0xFFFFFFFFu, sum, off);
        s_w[tid] = ev / sum;
    }
    __syncthreads();

    if (tid < DD4) {
        const float4* XP4 = reinterpret_cast<const float4*>(g_XP);
        float4 acc = make_float4(0.f, 0.f, 0.f, 0.f);
#pragma unroll 8
        for (int o = 0; o < OO; o++) {
            const float w = s_w[o];
            const float4 v = XP4[s_p[o] * DD4 + tid];
            acc.x += w * v.x;
            acc.y += w * v.y;
            acc.z += w * v.z;
            acc.w += w * v.w;
        }
        reinterpret_cast<float4*>(g_Z)[q * DD4 + tid] = acc;
    }
}

// ---------------------------------------------------------------------------
// K2: deterministic gather-fold. Each z element maps to exactly one output
// pixel, so out[c,h,w] = sum over the <=16 patches covering (h,w).
// Writes EVERY output element (handles 0xAA poison; uncovered row/col 255 -> 0).
// ---------------------------------------------------------------------------
__global__ void fold_kernel(float* __restrict__ out) {
    int idx = blockIdx.x * blockDim.x + threadIdx.x;
    if (idx >= CC * HH * WW) return;
    const int c = idx >> 16;          // / (256*256)
    const int h = (idx >> 8) & 255;
    const int w = idx & 255;

    // valid i: 0 <= h - 2i <= 6  ->  ceil((h-6)/2) <= i <= floor(h/2), clamped
    const int ilo = max(0, (h - 5) >> 1);     // arithmetic shift floors negatives
    const int ihi = min(NN - 1, h >> 1);
    const int jlo = max(0, (w - 5) >> 1);
    const int jhi = min(NN - 1, w >> 1);

    float acc = 0.f;
    for (int i = ilo; i <= ihi; i++) {
        const int r = h - 2 * i;
        const int rowbase = i * NN * DD + c * 49 + r * 7;
        for (int j = jlo; j <= jhi; j++) {
            const int s = w - 2 * j;
            acc += g_Z[rowbase + j * DD + s];
        }
    }
    out[idx] = acc;
}

// ---------------------------------------------------------------------------
extern "C" void kernel_launch(void* const* d_in, const int* in_sizes, int n_in,
                              void* d_out, int out_size) {
    const float* x    = (const float*)d_in[0];
    const float* xe   = (const float*)d_in[1];
    const float* ye   = (const float*)d_in[2];
    const int*   inds = (const int*)  d_in[3];
    float*       out  = (float*)d_out;
    (void)in_sizes; (void)n_in; (void)out_size;

    {   // K0: unfold
        const int total = NQ * DD;
        unfold_kernel<<<(total + 255) / 256, 256>>>(x);
    }
    {   // K1: fused dist + softmax + aggregate, one CTA per query
        agg_kernel<<<NQ, 64>>>(xe, ye, inds);
    }
    {   // K2: gather fold
        const int total = CC * HH * WW;
        fold_kernel<<<(total + 255) / 256, 256>>>(out);
    }
}

// round 2
// speedup vs baseline: 1.5320x; 1.5320x over previous
#include <cuda_runtime.h>

// Problem constants (fixed by setup_inputs)
#define CC      4
#define HH      256
#define WW      256
#define PS      7
#define STRIDE  2
#define EE      32
#define OO      32
#define NN      125                  // (256-7)/2+1
#define NQ      (NN * NN)            // 15625 queries/patches
#define DD      196                  // C*ps*ps
#define DIST_SCALE 10.0f
#define W_THR   1e-7f                // dropped softmax mass <= 32*1e-7 -> err ~1e-5 << 1e-3

__device__ float g_Z[NQ * DD];       // aggregated patches [q][d], d = c*49 + r*7 + s

// ---------------------------------------------------------------------------
// K1: one warp per query.
//  phase 1: lane o -> d2(ye[q], xe[inds[q,o]]) via 8x float4 loads + ye shuffle
//  phase 2: warp softmax; ballot-compact survivors (w >= W_THR) into shared
//  phase 3: gather surviving patches DIRECTLY from x (L2-resident, ~1.5/query)
//           lane handles d = t*32+lane, t=0..6; coalesced z store.
// ---------------------------------------------------------------------------
__global__ __launch_bounds__(256) void agg_kernel(const float* __restrict__ x,
                                                  const float* __restrict__ xe,
                                                  const float* __restrict__ ye,
                                                  const int*   __restrict__ inds) {
    const int lane = threadIdx.x & 31;
    const int wrp  = threadIdx.x >> 5;
    const int q    = blockIdx.x * 8 + wrp;
    if (q >= NQ) return;                         // warp-uniform; no block syncs used

    __shared__ float s_w[8][OO];
    __shared__ int   s_p[8][OO];

    // ---- phase 1: squared distance for candidate `lane` ----
    const float yl = ye[q * EE + lane];          // coalesced; broadcast via shfl
    const int   p  = inds[q * OO + lane];
    const float4* xr = reinterpret_cast<const float4*>(xe + p * EE);
    float d2 = 0.f;
#pragma unroll
    for (int k = 0; k < EE / 4; k++) {
        float4 a = xr[k];
        float b0 = __shfl_sync(0xFFFFFFFFu, yl, 4 * k + 0);
        float b1 = __shfl_sync(0xFFFFFFFFu, yl, 4 * k + 1);
        float b2 = __shfl_sync(0xFFFFFFFFu, yl, 4 * k + 2);
        float b3 = __shfl_sync(0xFFFFFFFFu, yl, 4 * k + 3);
        float dx = a.x - b0, dy = a.y - b1, dz = a.z - b2, dw = a.w - b3;
        d2 += dx * dx + dy * dy + dz * dz + dw * dw;
    }

    // ---- phase 2: softmax + threshold compaction ----
    float m = d2;
#pragma unroll
    for (int off = 16; off; off >>= 1)
        m = fminf(m, __shfl_xor_sync(0xFFFFFFFFu, m, off));
    float ev = __expf(-DIST_SCALE * (d2 - m));
    float sum = ev;
#pragma unroll
    for (int off = 16; off; off >>= 1)
        sum += __shfl_xor_sync(0xFFFFFFFFu, sum, off);
    const float w = ev / sum;

    const unsigned surv = __ballot_sync(0xFFFFFFFFu, w >= W_THR);
    const int k_surv = __popc(surv);
    if (w >= W_THR) {
        const int rank = __popc(surv & ((1u << lane) - 1u));
        s_w[wrp][rank] = w;
        s_p[wrp][rank] = p;
    }
    __syncwarp();

    // ---- phase 3: direct gather-aggregate from x ----
    // lane's elements: d = t*32 + lane ; off(d) = c*65536 + r*256 + s
    int   offs[7];
    bool  val[7];
#pragma unroll
    for (int t = 0; t < 7; t++) {
        int d = t * 32 + lane;
        val[t] = (d < DD);
        int dc = val[t] ? d : 0;
        int c  = dc / 49;
        int rs = dc - c * 49;
        int r  = rs / 7;
        int s  = rs - r * 7;
        offs[t] = c * (HH * WW) + r * WW + s;
    }

    float acc[7] = {0.f, 0.f, 0.f, 0.f, 0.f, 0.f, 0.f};
    for (int s = 0; s < k_surv; s++) {
        const float ws = s_w[wrp][s];
        const int   ps_ = s_p[wrp][s];
        const int   pi = ps_ / NN;
        const int   pj = ps_ - pi * NN;
        const int   base = pi * (STRIDE * WW) + pj * STRIDE;
#pragma unroll
        for (int t = 0; t < 7; t++)
            if (val[t]) acc[t] += ws * __ldg(&x[base + offs[t]]);
    }

    float* zq = g_Z + q * DD;
#pragma unroll
    for (int t = 0; t < 7; t++) {
        int d = t * 32 + lane;
        if (d < DD) zq[d] = acc[t];
    }
}

// ---------------------------------------------------------------------------
// K2: deterministic gather-fold. out[c,h,w] = sum of the <=16 covering patches.
// Writes EVERY output element (poison-safe; uncovered h/w=255 -> 0).
// ---------------------------------------------------------------------------
__global__ void fold_kernel(float* __restrict__ out) {
    int idx = blockIdx.x * blockDim.x + threadIdx.x;
    if (idx >= CC * HH * WW) return;
    const int c = idx >> 16;
    const int h = (idx >> 8) & 255;
    const int w = idx & 255;

    const int ilo = max(0, (h - 5) >> 1);
    const int ihi = min(NN - 1, h >> 1);
    const int jlo = max(0, (w - 5) >> 1);
    const int jhi = min(NN - 1, w >> 1);

    float acc = 0.f;
    for (int i = ilo; i <= ihi; i++) {
        const int r = h - 2 * i;
        const int rowbase = i * NN * DD + c * 49 + r * 7;
#pragma unroll 4
        for (int j = jlo; j <= jhi; j++) {
            const int s = w - 2 * j;
            acc += __ldg(&g_Z[rowbase + j * DD + s]);
        }
    }
    out[idx] = acc;
}

// ---------------------------------------------------------------------------
extern "C" void kernel_launch(void* const* d_in, const int* in_sizes, int n_in,
                              void* d_out, int out_size) {
    const float* x    = (const float*)d_in[0];
    const float* xe   = (const float*)d_in[1];
    const float* ye   = (const float*)d_in[2];
    const int*   inds = (const int*)  d_in[3];
    float*       out  = (float*)d_out;
    (void)in_sizes; (void)n_in; (void)out_size;

    agg_kernel<<<(NQ + 7) / 8, 256>>>(x, xe, ye, inds);

    const int total = CC * HH * WW;
    fold_kernel<<<(total + 255) / 256, 256>>>(out);
}

// round 3
// speedup vs baseline: 1.9671x; 1.2840x over previous
#include <cuda_runtime.h>

// Problem constants (fixed by setup_inputs)
#define CC      4
#define HH      256
#define WW      256
#define PS      7
#define STRIDE  2
#define EE      32
#define OO      32
#define NN      125                  // (256-7)/2+1
#define NQ      (NN * NN)            // 15625
#define DD      196                  // C*ps*ps
#define DIST_SCALE 10.0f
#define W_THR   1e-7f
#define FULL    0xFFFFFFFFu

// Transposed aggregation scratch: zT[d][q]
__device__ float g_ZT[DD * NQ];

// ---------------------------------------------------------------------------
// K1: 8 queries per 256-thread CTA (warp = query).
//  phase 1: coalesced candidate distances — 8 lanes per candidate row (float4
//           chunks), 4 candidates per LDG.128 -> 4 fully-consumed lines/instr.
//  phase 2: warp softmax + threshold compaction (deterministic rank order).
//  phase 3: paired-lane float2 patch gather from x; accumulate in smem.
//  phase 4: cooperative transposed store zT[d][q0..q0+7].
// ---------------------------------------------------------------------------
__global__ __launch_bounds__(256) void agg_kernel(const float* __restrict__ x,
                                                  const float* __restrict__ xe,
                                                  const float* __restrict__ ye,
                                                  const int*   __restrict__ inds) {
    const int lane = threadIdx.x & 31;
    const int wrp  = threadIdx.x >> 5;
    const int q0   = blockIdx.x * 8;
    const int q    = q0 + wrp;

    __shared__ float s_z [8][DD];    // per-query aggregated patch
    __shared__ float s_d2[8][OO];
    __shared__ float s_w [8][OO];
    __shared__ int   s_p [8][OO];

    if (q < NQ) {
        // ---- phase 1: distances, coalesced ----
        const int   g  = lane >> 3;          // candidate-group within instr
        const int   ch = lane & 7;           // float4 chunk of the row
        const float4 y4 = reinterpret_cast<const float4*>(ye + q * EE)[ch];
        const int   p_l = inds[q * OO + lane];

        float acck[8];
#pragma unroll
        for (int k = 0; k < 8; k++) {
            const int o  = k * 4 + g;
            const int po = __shfl_sync(FULL, p_l, o);
            const float4 v = reinterpret_cast<const float4*>(xe + po * EE)[ch];
            const float dx = v.x - y4.x, dy = v.y - y4.y;
            const float dz = v.z - y4.z, dw = v.w - y4.w;
            acck[k] = dx * dx + dy * dy + dz * dz + dw * dw;
        }
#pragma unroll
        for (int k = 0; k < 8; k++) {
            acck[k] += __shfl_xor_sync(FULL, acck[k], 1);
            acck[k] += __shfl_xor_sync(FULL, acck[k], 2);
            acck[k] += __shfl_xor_sync(FULL, acck[k], 4);
        }
        if (ch == 0) {
#pragma unroll
            for (int k = 0; k < 8; k++) s_d2[wrp][k * 4 + g] = acck[k];
        }
        __syncwarp();
        const float d2 = s_d2[wrp][lane];

        // ---- phase 2: softmax + compaction ----
        float m = d2;
#pragma unroll
        for (int off = 16; off; off >>= 1)
            m = fminf(m, __shfl_xor_sync(FULL, m, off));
        const float ev = __expf(-DIST_SCALE * (d2 - m));
        float sum = ev;
#pragma unroll
        for (int off = 16; off; off >>= 1)
            sum += __shfl_xor_sync(FULL, sum, off);
        const float w = ev / sum;

        const unsigned surv = __ballot_sync(FULL, w >= W_THR);
        const int k_surv = __popc(surv);
        if (w >= W_THR) {
            const int rank = __popc(surv & ((1u << lane) - 1u));
            s_w[wrp][rank] = w;
            s_p[wrp][rank] = p_l;
        }
        __syncwarp();

        // ---- phase 3: paired-lane patch gather ----
        // pass A: rows 0..15, pass B: rows 16..27 (lanes < 24)
        const int half = lane & 1;
        const int rcA  = lane >> 1;              // 0..15
        const int rcB  = 16 + (lane >> 1);       // 16..27 (lane<24)
        const int cA = rcA / 7, rA = rcA - cA * 7;
        const int cB = rcB / 7, rB = rcB - cB * 7;
        const int offA = cA * (HH * WW) + rA * WW;
        const int offB = cB * (HH * WW) + rB * WW;
        const int h4 = half * 4;

        float accA0 = 0.f, accA1 = 0.f, accA2 = 0.f, accA3 = 0.f;
        float accB0 = 0.f, accB1 = 0.f, accB2 = 0.f, accB3 = 0.f;

        for (int s = 0; s < k_surv; s++) {
            const float ws = s_w[wrp][s];
            const int   pp = s_p[wrp][s];
            const int   pi = pp / NN;
            const int   pj = pp - pi * NN;
            const int   pb = pi * (STRIDE * WW) + pj * STRIDE;  // even

            {   // pass A (all 32 lanes)
                const int base = offA + pb;
                const float2 a = *reinterpret_cast<const float2*>(x + base + h4);
                const float2 b = *reinterpret_cast<const float2*>(x + base + h4 + 2);
                accA0 += ws * a.x; accA1 += ws * a.y;
                accA2 += ws * b.x; accA3 += ws * b.y;
            }
            if (lane < 24) {   // pass B
                const int base = offB + pb;
                const float2 a = *reinterpret_cast<const float2*>(x + base + h4);
                const float2 b = *reinterpret_cast<const float2*>(x + base + h4 + 2);
                accB0 += ws * a.x; accB1 += ws * a.y;
                accB2 += ws * b.x; accB3 += ws * b.y;
            }
        }

        {   // half0 holds s0..s3 of its row, half1 holds s4..s6 (s7 discarded)
            const int d0 = rcA * 7 + h4;
            s_z[wrp][d0 + 0] = accA0;
            s_z[wrp][d0 + 1] = accA1;
            s_z[wrp][d0 + 2] = accA2;
            if (!half) s_z[wrp][d0 + 3] = accA3;
        }
        if (lane < 24) {
            const int d0 = rcB * 7 + h4;
            s_z[wrp][d0 + 0] = accB0;
            s_z[wrp][d0 + 1] = accB1;
            s_z[wrp][d0 + 2] = accB2;
            if (!half) s_z[wrp][d0 + 3] = accB3;
        }
    }

    __syncthreads();

    // ---- phase 4: transposed store zT[d][q0+ql] ----
#pragma unroll
    for (int t = threadIdx.x; t < DD * 8; t += 256) {
        const int d  = t >> 3;
        const int ql = t & 7;
        if (q0 + ql < NQ)
            g_ZT[d * NQ + q0 + ql] = s_z[ql][d];
    }
}

// ---------------------------------------------------------------------------
// K2: gather-fold from transposed z. out[c,h,w] = sum over covering patches.
// Inner addresses are consecutive in j -> coalesced-ish warps.
// Writes EVERY output element (poison-safe).
// ---------------------------------------------------------------------------
__global__ void fold_kernel(float* __restrict__ out) {
    int idx = blockIdx.x * blockDim.x + threadIdx.x;
    if (idx >= CC * HH * WW) return;
    const int c = idx >> 16;
    const int h = (idx >> 8) & 255;
    const int w = idx & 255;

    const int ilo = max(0, (h - 5) >> 1);
    const int ihi = min(NN - 1, h >> 1);
    const int jlo = max(0, (w - 5) >> 1);
    const int jhi = min(NN - 1, w >> 1);

    float acc = 0.f;
    for (int i = ilo; i <= ihi; i++) {
        const int r = h - 2 * i;
        const long dbase = (long)(c * 49 + r * 7) * NQ + i * NN;
#pragma unroll 4
        for (int j = jlo; j <= jhi; j++) {
            const int s = w - 2 * j;
            acc += __ldg(&g_ZT[dbase + (long)s * NQ + j]);
        }
    }
    out[idx] = acc;
}

// ---------------------------------------------------------------------------
extern "C" void kernel_launch(void* const* d_in, const int* in_sizes, int n_in,
                              void* d_out, int out_size) {
    const float* x    = (const float*)d_in[0];
    const float* xe   = (const float*)d_in[1];
    const float* ye   = (const float*)d_in[2];
    const int*   inds = (const int*)  d_in[3];
    float*       out  = (float*)d_out;
    (void)in_sizes; (void)n_in; (void)out_size;

    agg_kernel<<<(NQ + 7) / 8, 256>>>(x, xe, ye, inds);

    const int total = CC * HH * WW;
    fold_kernel<<<(total + 255) / 256, 256>>>(out);
}